// round 14
// baseline (speedup 1.0000x reference)
#include <cuda_runtime.h>
#include <cuda_bf16.h>
#include <cuda_fp16.h>
#include <cstdint>

// Problem constants
#define BB 1024
#define RR 8
#define CC 1024
#define KK 32
#define DD 16384
#define NCAND 40
#define SSTB 80         // smem row stride in BYTES (16B-aligned, LDSM conflict-free)
#define NSTG 4          // cp.async pipeline depth
#define STG_BYTES (128 * SSTB)                 // bytes per operand-stage (10240)
#define GEMM_SMEM (NSTG * 2 * STG_BYTES)       // 81920 bytes

// ---------------- device scratch (allocation-free rule: __device__ globals) ----
__device__ __half         g_h  [(size_t)BB * RR * DD];       // 256 MB approx h (fp16)
__device__ float          g_xc [(size_t)BB * RR * CC];       // 32 MB  x - decoder_b (fp32)
__device__ __nv_bfloat16  g_Ah [(size_t)RR * BB * CC];       // 16 MB  bf16 acts [r][b][c]
__device__ __nv_bfloat16  g_Bh [(size_t)RR * DD * CC];       // 256 MB bf16 weights [r][d][c]
__device__ float          g_dwT[(size_t)RR * DD * CC];       // 512 MB decoder_w transposed

// ---------------- prep ----------------------------------------------------------
__global__ void prep_x_kernel(const float* __restrict__ x,
                              const float* __restrict__ db) {
    int idx = blockIdx.x * blockDim.x + threadIdx.x;
    int b = idx >> 13;
    int r = (idx >> 10) & 7;
    int c = idx & 1023;
    float xc = x[idx] - db[r * CC + c];
    g_xc[idx] = xc;
    g_Ah[((size_t)r * BB + b) * CC + c] = __float2bfloat16(xc);
}

__global__ void prep_w_kernel(const float* __restrict__ ew) {
    int idx = blockIdx.x * blockDim.x + threadIdx.x;   // over R*D*C/8
    const float4* e4 = (const float4*)ew;
    float4 w0 = e4[2 * idx];
    float4 w1 = e4[2 * idx + 1];
    __nv_bfloat162 p0, p1, p2, p3;
    p0.x = __float2bfloat16(w0.x); p0.y = __float2bfloat16(w0.y);
    p1.x = __float2bfloat16(w0.z); p1.y = __float2bfloat16(w0.w);
    p2.x = __float2bfloat16(w1.x); p2.y = __float2bfloat16(w1.y);
    p3.x = __float2bfloat16(w1.z); p3.y = __float2bfloat16(w1.w);
    uint4 out;
    out.x = *(uint32_t*)&p0; out.y = *(uint32_t*)&p1;
    out.z = *(uint32_t*)&p2; out.w = *(uint32_t*)&p3;
    ((uint4*)g_Bh)[idx] = out;
}

__global__ void transpose_dw_kernel(const float* __restrict__ dw) {
    __shared__ float tile[32][33];
    int d0 = blockIdx.x * 32;
    int c0 = blockIdx.y * 32;
    int r  = blockIdx.z;
    int tx = threadIdx.x, ty = threadIdx.y;
    #pragma unroll
    for (int j = 0; j < 4; j++) {
        int c = c0 + ty + j * 8;
        tile[ty + j * 8][tx] = dw[((size_t)r * CC + c) * DD + d0 + tx];
    }
    __syncthreads();
    #pragma unroll
    for (int j = 0; j < 4; j++) {
        int d = d0 + ty + j * 8;
        g_dwT[((size_t)r * DD + d) * CC + c0 + tx] = tile[tx][ty + j * 8];
    }
}

// ---------------- encoder GEMM: bf16 mma m16n8k16, 4-stage cp.async + ldmatrix --
// Block 128x128, 8 warps (2x4), warp tile 64x32. Fully-unrolled K loop.

__device__ __forceinline__ void mma16816(float* c, const uint32_t* a,
                                         uint32_t b0, uint32_t b1) {
    asm volatile(
        "mma.sync.aligned.m16n8k16.row.col.f32.bf16.bf16.f32 "
        "{%0,%1,%2,%3}, {%4,%5,%6,%7}, {%8,%9}, {%0,%1,%2,%3};\n"
        : "+f"(c[0]), "+f"(c[1]), "+f"(c[2]), "+f"(c[3])
        : "r"(a[0]), "r"(a[1]), "r"(a[2]), "r"(a[3]), "r"(b0), "r"(b1));
}

__device__ __forceinline__ void ldsm4(uint32_t* d, uint32_t addr) {
    asm volatile("ldmatrix.sync.aligned.m8n8.x4.shared.b16 {%0,%1,%2,%3}, [%4];"
                 : "=r"(d[0]), "=r"(d[1]), "=r"(d[2]), "=r"(d[3]) : "r"(addr));
}

__device__ __forceinline__ void cp16(uint32_t dst, const void* src) {
    asm volatile("cp.async.cg.shared.global [%0], [%1], 16;\n"
                 :: "r"(dst), "l"(src) : "memory");
}

__global__ __launch_bounds__(256, 2)
void encoder_gemm_kernel(const __nv_bfloat16* __restrict__ Ap,
                         const __nv_bfloat16* __restrict__ Bp,
                         const float* __restrict__ eb,
                         __half* __restrict__ H) {
    extern __shared__ uint8_t smem[];   // [NSTG][A|B][128*SSTB]
    const int mt = blockIdx.x;        // 8  (fastest: B-tile L2 reuse)
    const int nt = blockIdx.y;        // 128
    const int r  = blockIdx.z;        // 8
    const int tid = threadIdx.x;
    const int wid = tid >> 5, lane = tid & 31;
    const int wm = wid >> 2, wn = wid & 3;    // 2x4 warps, 64x32 per warp
    const int g = lane >> 2, t = lane & 3;

    float acc[4][4][4];
    #pragma unroll
    for (int i = 0; i < 4; i++)
        #pragma unroll
        for (int j = 0; j < 4; j++)
            #pragma unroll
            for (int q = 0; q < 4; q++) acc[i][j][q] = 0.f;

    const uint32_t s0 = (uint32_t)__cvta_generic_to_shared(smem);

    // global->smem: per operand-stage 128 rows x 64B = 512 x 16B; 2 per thread
    const int row0 = tid >> 2, seg0 = (tid & 3) * 8;            // seg in bf16 elems
    const int row1 = (tid + 256) >> 2, seg1 = ((tid + 256) & 3) * 8;
    const uint32_t d0b = (uint32_t)(row0 * SSTB + seg0 * 2);
    const uint32_t d1b = (uint32_t)(row1 * SSTB + seg1 * 2);

    // running global pointers (advance +32 elems per prefetched chunk)
    const __nv_bfloat16* pa0 = Ap + ((size_t)r * BB + (size_t)mt * 128 + row0) * CC + seg0;
    const __nv_bfloat16* pa1 = Ap + ((size_t)r * BB + (size_t)mt * 128 + row1) * CC + seg1;
    const __nv_bfloat16* pb0 = Bp + ((size_t)r * DD + (size_t)nt * 128 + row0) * CC + seg0;
    const __nv_bfloat16* pb1 = Bp + ((size_t)r * DD + (size_t)nt * 128 + row1) * CC + seg1;

    // ldmatrix lane offsets (bytes within operand-stage)
    const uint32_t aF = (uint32_t)((wm * 64 + (lane & 15)) * SSTB + (lane >> 4) * 16);
    const uint32_t bF = (uint32_t)((wn * 32 + (lane & 15)) * SSTB + (lane >> 4) * 16);

    #pragma unroll
    for (int p = 0; p < NSTG - 1; p++) {
        uint32_t aB = s0 + p * (2 * STG_BYTES);
        cp16(aB + d0b, pa0); cp16(aB + d1b, pa1);
        cp16(aB + STG_BYTES + d0b, pb0); cp16(aB + STG_BYTES + d1b, pb1);
        pa0 += 32; pa1 += 32; pb0 += 32; pb1 += 32;
        asm volatile("cp.async.commit_group;" ::: "memory");
    }

    const int NKT = CC / 32;   // 32
    #pragma unroll
    for (int kt = 0; kt < NKT; kt++) {
        asm volatile("cp.async.wait_group %0;" :: "n"(NSTG - 2) : "memory");
        __syncthreads();
        if (kt + NSTG - 1 < NKT) {
            const uint32_t aB = s0 + ((kt + NSTG - 1) & (NSTG - 1)) * (2 * STG_BYTES);
            cp16(aB + d0b, pa0); cp16(aB + d1b, pa1);
            cp16(aB + STG_BYTES + d0b, pb0); cp16(aB + STG_BYTES + d1b, pb1);
            pa0 += 32; pa1 += 32; pb0 += 32; pb1 += 32;
        }
        asm volatile("cp.async.commit_group;" ::: "memory");

        const uint32_t baseA = s0 + (kt & (NSTG - 1)) * (2 * STG_BYTES) + aF;
        const uint32_t baseB = s0 + (kt & (NSTG - 1)) * (2 * STG_BYTES) + STG_BYTES + bF;
        #pragma unroll
        for (int ks = 0; ks < 2; ks++) {          // two k16 steps per 64B row
            const int ko = ks * 32;               // byte offset (16 bf16)
            uint32_t afr[4][4], bq[2][4];
            #pragma unroll
            for (int mi = 0; mi < 4; mi++) ldsm4(afr[mi], baseA + mi * 16 * SSTB + ko);
            #pragma unroll
            for (int nb = 0; nb < 2; nb++) ldsm4(bq[nb], baseB + nb * 16 * SSTB + ko);
            #pragma unroll
            for (int mi = 0; mi < 4; mi++)
                #pragma unroll
                for (int nb = 0; nb < 2; nb++) {
                    mma16816(acc[mi][2 * nb],     afr[mi], bq[nb][0], bq[nb][2]);
                    mma16816(acc[mi][2 * nb + 1], afr[mi], bq[nb][1], bq[nb][3]);
                }
        }
    }

    // epilogue: h = acc + encoder_b -> fp16
    const size_t ebBase = (size_t)r * DD;
    #pragma unroll
    for (int mi = 0; mi < 4; mi++) {
        int b0 = mt * 128 + wm * 64 + mi * 16 + g;
        #pragma unroll
        for (int ni = 0; ni < 4; ni++) {
            int dd0 = nt * 128 + wn * 32 + ni * 8 + 2 * t;
            float e0 = eb[ebBase + dd0];
            float e1 = eb[ebBase + dd0 + 1];
            __half2 v0, v1;
            v0.x = __float2half(acc[mi][ni][0] + e0);
            v0.y = __float2half(acc[mi][ni][1] + e1);
            v1.x = __float2half(acc[mi][ni][2] + e0);
            v1.y = __float2half(acc[mi][ni][3] + e1);
            *(__half2*)&H[((size_t)b0 * RR + r) * DD + dd0]       = v0;
            *(__half2*)&H[((size_t)(b0 + 8) * RR + r) * DD + dd0] = v1;
        }
    }
}

// ---------------- fused select (topk->refine) + decode, one block per row -------
// block = r*BB + b (r-major: same-r blocks adjacent -> ew[r]/dwT[r] L2-resident)
__global__ __launch_bounds__(256)
void select_decode_kernel(const __half* __restrict__ H,
                          const float* __restrict__ ew,
                          const float* __restrict__ eb,
                          const float* __restrict__ db,
                          float* __restrict__ out) {
    __shared__ float sxc[CC];                 // 4 KB xc row
    __shared__ int   s_warp[8];
    __shared__ int   s_total, s_cnt, s_tiecnt;
    __shared__ int   scand[NCAND];
    __shared__ float sval[NCAND];
    __shared__ int   tie_idx[160];
    __shared__ float s_wval[KK];
    __shared__ int   s_widx[KK];

    const int r = blockIdx.x >> 10;
    const int b = blockIdx.x & 1023;
    const size_t row = (size_t)b * RR + r;            // h/xc/out row
    const int tid = threadIdx.x;              // 256 threads
    const int wid = tid >> 5, lane = tid & 31;

    // ---- phase 0: load xc row + h keys ----
    for (int i = tid; i < CC; i += 256) sxc[i] = g_xc[row * CC + i];

    const uint4* h4 = (const uint4*)(H + row * DD);
    uint32_t kreg[32];                        // 64 fp16 per thread, sortable u16 x2
    #pragma unroll
    for (int c = 0; c < 8; c++) {
        uint4 v = h4[tid + c * 256];
        uint32_t w[4] = {v.x, v.y, v.z, v.w};
        #pragma unroll
        for (int q = 0; q < 4; q++) {
            uint32_t x = w[q];
            uint32_t neg = (x >> 15) & 0x00010001u;
            kreg[c * 4 + q] = x ^ (0x80008000u | (neg * 0x7FFFu));
        }
    }

    // ---- phase 1: bisection for NCAND-th key ----
    int lo = -1, hi = 65535;
    for (int it = 0; it < 16; it++) {
        int mid = (lo + hi) >> 1;
        uint32_t m2 = (uint32_t)mid * 0x00010001u;
        uint32_t accv = 0;
        #pragma unroll
        for (int i = 0; i < 32; i++) accv += __vsetgtu2(kreg[i], m2);
        int cnt = (int)((accv & 0xFFFF) + (accv >> 16));
        #pragma unroll
        for (int o = 16; o > 0; o >>= 1) cnt += __shfl_xor_sync(0xFFFFFFFFu, cnt, o);
        if (lane == 0) s_warp[wid] = cnt;
        __syncthreads();
        if (tid == 0) {
            int tot = 0;
            #pragma unroll
            for (int w = 0; w < 8; w++) tot += s_warp[w];
            s_total = tot;
        }
        __syncthreads();
        if (s_total < NCAND) hi = mid; else lo = mid;
        __syncthreads();
    }
    const uint32_t T = (uint32_t)hi;

    if (tid == 0) { s_cnt = 0; s_tiecnt = 0; }
    __syncthreads();

    #pragma unroll
    for (int c = 0; c < 8; c++) {
        int ibase = (tid + c * 256) * 8;
        #pragma unroll
        for (int q = 0; q < 4; q++) {
            uint32_t k2 = kreg[c * 4 + q];
            uint32_t klo = k2 & 0xFFFF, khi = k2 >> 16;
            if (klo > T)       { int p = atomicAdd(&s_cnt, 1);    scand[p] = ibase + 2 * q; }
            else if (klo == T) { int p = atomicAdd(&s_tiecnt, 1); if (p < 160) tie_idx[p] = ibase + 2 * q; }
            if (khi > T)       { int p = atomicAdd(&s_cnt, 1);    scand[p] = ibase + 2 * q + 1; }
            else if (khi == T) { int p = atomicAdd(&s_tiecnt, 1); if (p < 160) tie_idx[p] = ibase + 2 * q + 1; }
        }
    }
    __syncthreads();
    if (tid == 0) {
        int gcnt = s_cnt;
        int need = NCAND - gcnt;              // >= 1
        for (int a = 0; a < need; a++) scand[gcnt + a] = tie_idx[a];
    }
    __syncthreads();

    // ---- phase 2: exact fp32 refine of NCAND candidates ----
    const float4* xs4 = (const float4*)sxc;
    #pragma unroll
    for (int j = 0; j < NCAND / 8; j++) {
        int ci = j * 8 + wid;                 // 5 rounds x 8 warps = 40
        int d = scand[ci];
        const float4* wr = (const float4*)(ew + ((size_t)r * DD + d) * CC);
        float acc = 0.f;
        #pragma unroll
        for (int it = 0; it < 8; it++) {
            float4 a = xs4[it * 32 + lane];
            float4 bv = wr[it * 32 + lane];
            acc += a.x * bv.x;
            acc += a.y * bv.y;
            acc += a.z * bv.z;
            acc += a.w * bv.w;
        }
        #pragma unroll
        for (int o = 16; o > 0; o >>= 1)
            acc += __shfl_xor_sync(0xFFFFFFFFu, acc, o);
        if (lane == 0) sval[ci] = acc + eb[(size_t)r * DD + d];
    }
    __syncthreads();

    // rank top-KK by (value desc, index asc); relu the values
    if (tid < NCAND) {
        float v = sval[tid];
        int   d = scand[tid];
        int rank = 0;
        #pragma unroll
        for (int j = 0; j < NCAND; j++) {
            float vj = sval[j];
            int   dj = scand[j];
            rank += (vj > v) || (vj == v && dj < d);
        }
        if (rank < KK) {
            s_widx[rank] = d;
            s_wval[rank] = v > 0.f ? v : 0.f;
        }
    }
    __syncthreads();

    // ---- phase 3: decode out = db + sum_j val_j * dwT[r][idx_j][:] ----
    const float4* dwr4 = (const float4*)(g_dwT + (size_t)r * DD * CC);
    float4 acc4 = ((const float4*)(db + (size_t)r * CC))[tid];
    #pragma unroll
    for (int j = 0; j < KK; j++) {
        float vj = s_wval[j];
        float4 w4 = dwr4[(size_t)s_widx[j] * (CC / 4) + tid];
        acc4.x += vj * w4.x;
        acc4.y += vj * w4.y;
        acc4.z += vj * w4.z;
        acc4.w += vj * w4.w;
    }
    ((float4*)(out + row * CC))[tid] = acc4;
}

// ---------------- launch ----------------------------------------------------------
extern "C" void kernel_launch(void* const* d_in, const int* in_sizes, int n_in,
                              void* d_out, int out_size) {
    const float* x  = (const float*)d_in[0];
    const float* ew = (const float*)d_in[1];
    const float* eb = (const float*)d_in[2];
    const float* dw = (const float*)d_in[3];
    const float* db = (const float*)d_in[4];
    float* out = (float*)d_out;

    __half* h_ptr;         cudaGetSymbolAddress((void**)&h_ptr, g_h);
    __nv_bfloat16* a_ptr;  cudaGetSymbolAddress((void**)&a_ptr, g_Ah);
    __nv_bfloat16* b_ptr;  cudaGetSymbolAddress((void**)&b_ptr, g_Bh);

    cudaFuncSetAttribute(encoder_gemm_kernel,
                         cudaFuncAttributeMaxDynamicSharedMemorySize, GEMM_SMEM);

    prep_x_kernel<<<(BB * RR * CC) / 256, 256>>>(x, db);
    prep_w_kernel<<<(RR * DD * CC) / 2048, 256>>>(ew);
    transpose_dw_kernel<<<dim3(DD / 32, CC / 32, RR), dim3(32, 8)>>>(dw);
    encoder_gemm_kernel<<<dim3(BB / 128, DD / 128, RR), 256, GEMM_SMEM>>>(a_ptr, b_ptr, eb, h_ptr);
    select_decode_kernel<<<BB * RR, 256>>>(h_ptr, ew, eb, db, out);
}

// round 15
// speedup vs baseline: 1.4771x; 1.4771x over previous
#include <cuda_runtime.h>
#include <cuda_bf16.h>
#include <cuda_fp16.h>
#include <cstdint>

// Problem constants
#define BB 1024
#define RR 8
#define CC 1024
#define KK 32
#define DD 16384
#define NCAND 40
#define SSTB 80         // smem row stride in BYTES (16B-aligned, LDSM conflict-free)
#define NSTG 4          // cp.async pipeline depth
#define STG_BYTES (128 * SSTB)                 // bytes per operand-stage (10240)
#define GEMM_SMEM (NSTG * 2 * STG_BYTES)       // 81920 bytes

// ---------------- device scratch (allocation-free rule: __device__ globals) ----
__device__ __half         g_h  [(size_t)BB * RR * DD];       // 256 MB approx h (fp16)
__device__ float          g_xc [(size_t)BB * RR * CC];       // 32 MB  x - decoder_b (fp32)
__device__ __nv_bfloat16  g_Ah [(size_t)RR * BB * CC];       // 16 MB  bf16 acts [r][b][c]
__device__ __nv_bfloat16  g_Bh [(size_t)RR * DD * CC];       // 256 MB bf16 weights [r][d][c]
__device__ float          g_dwT[(size_t)RR * DD * CC];       // 512 MB decoder_w transposed

// ---------------- prep ----------------------------------------------------------
__global__ void prep_x_kernel(const float* __restrict__ x,
                              const float* __restrict__ db) {
    int idx = blockIdx.x * blockDim.x + threadIdx.x;
    int b = idx >> 13;
    int r = (idx >> 10) & 7;
    int c = idx & 1023;
    float xc = x[idx] - db[r * CC + c];
    g_xc[idx] = xc;
    g_Ah[((size_t)r * BB + b) * CC + c] = __float2bfloat16(xc);
}

__global__ void prep_w_kernel(const float* __restrict__ ew) {
    int idx = blockIdx.x * blockDim.x + threadIdx.x;   // over R*D*C/8
    const float4* e4 = (const float4*)ew;
    float4 w0 = e4[2 * idx];
    float4 w1 = e4[2 * idx + 1];
    __nv_bfloat162 p0, p1, p2, p3;
    p0.x = __float2bfloat16(w0.x); p0.y = __float2bfloat16(w0.y);
    p1.x = __float2bfloat16(w0.z); p1.y = __float2bfloat16(w0.w);
    p2.x = __float2bfloat16(w1.x); p2.y = __float2bfloat16(w1.y);
    p3.x = __float2bfloat16(w1.z); p3.y = __float2bfloat16(w1.w);
    uint4 out;
    out.x = *(uint32_t*)&p0; out.y = *(uint32_t*)&p1;
    out.z = *(uint32_t*)&p2; out.w = *(uint32_t*)&p3;
    ((uint4*)g_Bh)[idx] = out;
}

__global__ void transpose_dw_kernel(const float* __restrict__ dw) {
    __shared__ float tile[32][33];
    int d0 = blockIdx.x * 32;
    int c0 = blockIdx.y * 32;
    int r  = blockIdx.z;
    int tx = threadIdx.x, ty = threadIdx.y;
    #pragma unroll
    for (int j = 0; j < 4; j++) {
        int c = c0 + ty + j * 8;
        tile[ty + j * 8][tx] = dw[((size_t)r * CC + c) * DD + d0 + tx];
    }
    __syncthreads();
    #pragma unroll
    for (int j = 0; j < 4; j++) {
        int d = d0 + ty + j * 8;
        g_dwT[((size_t)r * DD + d) * CC + c0 + tx] = tile[tx][ty + j * 8];
    }
}

// ---------------- encoder GEMM: bf16 mma m16n8k16, 4-stage cp.async + ldmatrix --
// Block 128x128, 8 warps (2x4), warp tile 64x32. Unroll-8 K loop (I$-safe).

__device__ __forceinline__ void mma16816(float* c, const uint32_t* a,
                                         uint32_t b0, uint32_t b1) {
    asm volatile(
        "mma.sync.aligned.m16n8k16.row.col.f32.bf16.bf16.f32 "
        "{%0,%1,%2,%3}, {%4,%5,%6,%7}, {%8,%9}, {%0,%1,%2,%3};\n"
        : "+f"(c[0]), "+f"(c[1]), "+f"(c[2]), "+f"(c[3])
        : "r"(a[0]), "r"(a[1]), "r"(a[2]), "r"(a[3]), "r"(b0), "r"(b1));
}

__device__ __forceinline__ void ldsm4(uint32_t* d, uint32_t addr) {
    asm volatile("ldmatrix.sync.aligned.m8n8.x4.shared.b16 {%0,%1,%2,%3}, [%4];"
                 : "=r"(d[0]), "=r"(d[1]), "=r"(d[2]), "=r"(d[3]) : "r"(addr));
}

__device__ __forceinline__ void cp16(uint32_t dst, const void* src) {
    asm volatile("cp.async.cg.shared.global [%0], [%1], 16;\n"
                 :: "r"(dst), "l"(src) : "memory");
}

__global__ __launch_bounds__(256, 2)
void encoder_gemm_kernel(const __nv_bfloat16* __restrict__ Ap,
                         const __nv_bfloat16* __restrict__ Bp,
                         const float* __restrict__ eb,
                         __half* __restrict__ H) {
    extern __shared__ uint8_t smem[];   // [NSTG][A|B][128*SSTB]
    const int mt = blockIdx.x;        // 8  (fastest: B-tile L2 reuse)
    const int nt = blockIdx.y;        // 128
    const int r  = blockIdx.z;        // 8
    const int tid = threadIdx.x;
    const int wid = tid >> 5, lane = tid & 31;
    const int wm = wid >> 2, wn = wid & 3;    // 2x4 warps, 64x32 per warp
    const int g = lane >> 2, t = lane & 3;

    float acc[4][4][4];
    #pragma unroll
    for (int i = 0; i < 4; i++)
        #pragma unroll
        for (int j = 0; j < 4; j++)
            #pragma unroll
            for (int q = 0; q < 4; q++) acc[i][j][q] = 0.f;

    const uint32_t s0 = (uint32_t)__cvta_generic_to_shared(smem);

    // global->smem: per operand-stage 128 rows x 64B = 512 x 16B; 2 per thread
    const int row0 = tid >> 2, seg0 = (tid & 3) * 8;            // seg in bf16 elems
    const int row1 = (tid + 256) >> 2, seg1 = ((tid + 256) & 3) * 8;
    const uint32_t d0b = (uint32_t)(row0 * SSTB + seg0 * 2);
    const uint32_t d1b = (uint32_t)(row1 * SSTB + seg1 * 2);

    // running global pointers (advance +32 elems per prefetched chunk)
    const __nv_bfloat16* pa0 = Ap + ((size_t)r * BB + (size_t)mt * 128 + row0) * CC + seg0;
    const __nv_bfloat16* pa1 = Ap + ((size_t)r * BB + (size_t)mt * 128 + row1) * CC + seg1;
    const __nv_bfloat16* pb0 = Bp + ((size_t)r * DD + (size_t)nt * 128 + row0) * CC + seg0;
    const __nv_bfloat16* pb1 = Bp + ((size_t)r * DD + (size_t)nt * 128 + row1) * CC + seg1;

    // ldmatrix lane offsets (bytes within operand-stage)
    const uint32_t aF = (uint32_t)((wm * 64 + (lane & 15)) * SSTB + (lane >> 4) * 16);
    const uint32_t bF = (uint32_t)((wn * 32 + (lane & 15)) * SSTB + (lane >> 4) * 16);

    #pragma unroll
    for (int p = 0; p < NSTG - 1; p++) {
        uint32_t aB = s0 + p * (2 * STG_BYTES);
        cp16(aB + d0b, pa0); cp16(aB + d1b, pa1);
        cp16(aB + STG_BYTES + d0b, pb0); cp16(aB + STG_BYTES + d1b, pb1);
        pa0 += 32; pa1 += 32; pb0 += 32; pb1 += 32;
        asm volatile("cp.async.commit_group;" ::: "memory");
    }

    const int NKT = CC / 32;   // 32
    #pragma unroll 8
    for (int kt = 0; kt < NKT; kt++) {
        asm volatile("cp.async.wait_group %0;" :: "n"(NSTG - 2) : "memory");
        __syncthreads();
        if (kt + NSTG - 1 < NKT) {
            const uint32_t aB = s0 + ((kt + NSTG - 1) & (NSTG - 1)) * (2 * STG_BYTES);
            cp16(aB + d0b, pa0); cp16(aB + d1b, pa1);
            cp16(aB + STG_BYTES + d0b, pb0); cp16(aB + STG_BYTES + d1b, pb1);
            pa0 += 32; pa1 += 32; pb0 += 32; pb1 += 32;
        }
        asm volatile("cp.async.commit_group;" ::: "memory");

        const uint32_t baseA = s0 + (kt & (NSTG - 1)) * (2 * STG_BYTES) + aF;
        const uint32_t baseB = s0 + (kt & (NSTG - 1)) * (2 * STG_BYTES) + STG_BYTES + bF;
        #pragma unroll
        for (int ks = 0; ks < 2; ks++) {          // two k16 steps per 64B row
            const int ko = ks * 32;               // byte offset (16 bf16)
            uint32_t afr[4][4], bq[2][4];
            #pragma unroll
            for (int mi = 0; mi < 4; mi++) ldsm4(afr[mi], baseA + mi * 16 * SSTB + ko);
            #pragma unroll
            for (int nb = 0; nb < 2; nb++) ldsm4(bq[nb], baseB + nb * 16 * SSTB + ko);
            #pragma unroll
            for (int mi = 0; mi < 4; mi++)
                #pragma unroll
                for (int nb = 0; nb < 2; nb++) {
                    mma16816(acc[mi][2 * nb],     afr[mi], bq[nb][0], bq[nb][2]);
                    mma16816(acc[mi][2 * nb + 1], afr[mi], bq[nb][1], bq[nb][3]);
                }
        }
    }

    // epilogue: h = acc + encoder_b -> fp16
    const size_t ebBase = (size_t)r * DD;
    #pragma unroll
    for (int mi = 0; mi < 4; mi++) {
        int b0 = mt * 128 + wm * 64 + mi * 16 + g;
        #pragma unroll
        for (int ni = 0; ni < 4; ni++) {
            int dd0 = nt * 128 + wn * 32 + ni * 8 + 2 * t;
            float e0 = eb[ebBase + dd0];
            float e1 = eb[ebBase + dd0 + 1];
            __half2 v0, v1;
            v0.x = __float2half(acc[mi][ni][0] + e0);
            v0.y = __float2half(acc[mi][ni][1] + e1);
            v1.x = __float2half(acc[mi][ni][2] + e0);
            v1.y = __float2half(acc[mi][ni][3] + e1);
            *(__half2*)&H[((size_t)b0 * RR + r) * DD + dd0]       = v0;
            *(__half2*)&H[((size_t)(b0 + 8) * RR + r) * DD + dd0] = v1;
        }
    }
}

// ---------------- fused select (topk->refine) + decode, one block per row -------
// block = r*BB + b (r-major: same-r blocks adjacent -> ew[r]/dwT[r] L2-resident)
__global__ __launch_bounds__(256)
void select_decode_kernel(const __half* __restrict__ H,
                          const float* __restrict__ ew,
                          const float* __restrict__ eb,
                          const float* __restrict__ db,
                          float* __restrict__ out) {
    __shared__ float sxc[CC];                 // 4 KB xc row
    __shared__ int   s_warp[8];
    __shared__ int   s_total, s_cnt, s_tiecnt;
    __shared__ int   scand[NCAND];
    __shared__ float sval[NCAND];
    __shared__ int   tie_idx[160];
    __shared__ float s_wval[KK];
    __shared__ int   s_widx[KK];

    const int r = blockIdx.x >> 10;
    const int b = blockIdx.x & 1023;
    const size_t row = (size_t)b * RR + r;            // h/xc/out row
    const int tid = threadIdx.x;              // 256 threads
    const int wid = tid >> 5, lane = tid & 31;

    // ---- phase 0: load xc row + h keys ----
    for (int i = tid; i < CC; i += 256) sxc[i] = g_xc[row * CC + i];

    const uint4* h4 = (const uint4*)(H + row * DD);
    uint32_t kreg[32];                        // 64 fp16 per thread, sortable u16 x2
    #pragma unroll
    for (int c = 0; c < 8; c++) {
        uint4 v = h4[tid + c * 256];
        uint32_t w[4] = {v.x, v.y, v.z, v.w};
        #pragma unroll
        for (int q = 0; q < 4; q++) {
            uint32_t x = w[q];
            uint32_t neg = (x >> 15) & 0x00010001u;
            kreg[c * 4 + q] = x ^ (0x80008000u | (neg * 0x7FFFu));
        }
    }

    // ---- phase 1: bisection for NCAND-th key ----
    int lo = -1, hi = 65535;
    for (int it = 0; it < 16; it++) {
        int mid = (lo + hi) >> 1;
        uint32_t m2 = (uint32_t)mid * 0x00010001u;
        uint32_t accv = 0;
        #pragma unroll
        for (int i = 0; i < 32; i++) accv += __vsetgtu2(kreg[i], m2);
        int cnt = (int)((accv & 0xFFFF) + (accv >> 16));
        #pragma unroll
        for (int o = 16; o > 0; o >>= 1) cnt += __shfl_xor_sync(0xFFFFFFFFu, cnt, o);
        if (lane == 0) s_warp[wid] = cnt;
        __syncthreads();
        if (tid == 0) {
            int tot = 0;
            #pragma unroll
            for (int w = 0; w < 8; w++) tot += s_warp[w];
            s_total = tot;
        }
        __syncthreads();
        if (s_total < NCAND) hi = mid; else lo = mid;
        __syncthreads();
    }
    const uint32_t T = (uint32_t)hi;

    if (tid == 0) { s_cnt = 0; s_tiecnt = 0; }
    __syncthreads();

    #pragma unroll
    for (int c = 0; c < 8; c++) {
        int ibase = (tid + c * 256) * 8;
        #pragma unroll
        for (int q = 0; q < 4; q++) {
            uint32_t k2 = kreg[c * 4 + q];
            uint32_t klo = k2 & 0xFFFF, khi = k2 >> 16;
            if (klo > T)       { int p = atomicAdd(&s_cnt, 1);    scand[p] = ibase + 2 * q; }
            else if (klo == T) { int p = atomicAdd(&s_tiecnt, 1); if (p < 160) tie_idx[p] = ibase + 2 * q; }
            if (khi > T)       { int p = atomicAdd(&s_cnt, 1);    scand[p] = ibase + 2 * q + 1; }
            else if (khi == T) { int p = atomicAdd(&s_tiecnt, 1); if (p < 160) tie_idx[p] = ibase + 2 * q + 1; }
        }
    }
    __syncthreads();
    if (tid == 0) {
        int gcnt = s_cnt;
        int need = NCAND - gcnt;              // >= 1
        for (int a = 0; a < need; a++) scand[gcnt + a] = tie_idx[a];
    }
    __syncthreads();

    // ---- phase 2: exact fp32 refine of NCAND candidates ----
    const float4* xs4 = (const float4*)sxc;
    #pragma unroll
    for (int j = 0; j < NCAND / 8; j++) {
        int ci = j * 8 + wid;                 // 5 rounds x 8 warps = 40
        int d = scand[ci];
        const float4* wr = (const float4*)(ew + ((size_t)r * DD + d) * CC);
        float acc = 0.f;
        #pragma unroll
        for (int it = 0; it < 8; it++) {
            float4 a = xs4[it * 32 + lane];
            float4 bv = wr[it * 32 + lane];
            acc += a.x * bv.x;
            acc += a.y * bv.y;
            acc += a.z * bv.z;
            acc += a.w * bv.w;
        }
        #pragma unroll
        for (int o = 16; o > 0; o >>= 1)
            acc += __shfl_xor_sync(0xFFFFFFFFu, acc, o);
        if (lane == 0) sval[ci] = acc + eb[(size_t)r * DD + d];
    }
    __syncthreads();

    // rank top-KK by (value desc, index asc); relu the values
    if (tid < NCAND) {
        float v = sval[tid];
        int   d = scand[tid];
        int rank = 0;
        #pragma unroll
        for (int j = 0; j < NCAND; j++) {
            float vj = sval[j];
            int   dj = scand[j];
            rank += (vj > v) || (vj == v && dj < d);
        }
        if (rank < KK) {
            s_widx[rank] = d;
            s_wval[rank] = v > 0.f ? v : 0.f;
        }
    }
    __syncthreads();

    // ---- phase 3: decode out = db + sum_j val_j * dwT[r][idx_j][:] ----
    const float4* dwr4 = (const float4*)(g_dwT + (size_t)r * DD * CC);
    float4 acc4 = ((const float4*)(db + (size_t)r * CC))[tid];
    #pragma unroll
    for (int j = 0; j < KK; j++) {
        float vj = s_wval[j];
        float4 w4 = dwr4[(size_t)s_widx[j] * (CC / 4) + tid];
        acc4.x += vj * w4.x;
        acc4.y += vj * w4.y;
        acc4.z += vj * w4.z;
        acc4.w += vj * w4.w;
    }
    ((float4*)(out + row * CC))[tid] = acc4;
}

// ---------------- launch ----------------------------------------------------------
extern "C" void kernel_launch(void* const* d_in, const int* in_sizes, int n_in,
                              void* d_out, int out_size) {
    const float* x  = (const float*)d_in[0];
    const float* ew = (const float*)d_in[1];
    const float* eb = (const float*)d_in[2];
    const float* dw = (const float*)d_in[3];
    const float* db = (const float*)d_in[4];
    float* out = (float*)d_out;

    __half* h_ptr;         cudaGetSymbolAddress((void**)&h_ptr, g_h);
    __nv_bfloat16* a_ptr;  cudaGetSymbolAddress((void**)&a_ptr, g_Ah);
    __nv_bfloat16* b_ptr;  cudaGetSymbolAddress((void**)&b_ptr, g_Bh);

    cudaFuncSetAttribute(encoder_gemm_kernel,
                         cudaFuncAttributeMaxDynamicSharedMemorySize, GEMM_SMEM);

    prep_x_kernel<<<(BB * RR * CC) / 256, 256>>>(x, db);
    prep_w_kernel<<<(RR * DD * CC) / 2048, 256>>>(ew);
    transpose_dw_kernel<<<dim3(DD / 32, CC / 32, RR), dim3(32, 8)>>>(dw);
    encoder_gemm_kernel<<<dim3(BB / 128, DD / 128, RR), 256, GEMM_SMEM>>>(a_ptr, b_ptr, eb, h_ptr);
    select_decode_kernel<<<BB * RR, 256>>>(h_ptr, ew, eb, db, out);
}

// round 16
// speedup vs baseline: 1.5167x; 1.0269x over previous
#include <cuda_runtime.h>
#include <cuda_bf16.h>
#include <cuda_fp16.h>
#include <cstdint>

// Problem constants
#define BB 1024
#define RR 8
#define CC 1024
#define KK 32
#define DD 16384
#define NCAND 40
#define SSTB 80         // smem row stride in BYTES (16B-aligned, LDSM conflict-free)
#define NSTG 4          // cp.async pipeline depth
#define STG_BYTES (128 * SSTB)                 // bytes per operand-stage (10240)
#define GEMM_SMEM (NSTG * 2 * STG_BYTES)       // 81920 bytes

// ---------------- device scratch (allocation-free rule: __device__ globals) ----
__device__ __half         g_h  [(size_t)BB * RR * DD];       // 256 MB approx h (fp16)
__device__ float          g_xc [(size_t)BB * RR * CC];       // 32 MB  x - decoder_b (fp32)
__device__ __nv_bfloat16  g_Ah [(size_t)RR * BB * CC];       // 16 MB  bf16 acts [r][b][c]
__device__ __nv_bfloat16  g_Bh [(size_t)RR * DD * CC];       // 256 MB bf16 weights [r][d][c]
__device__ __half         g_dwT[(size_t)RR * DD * CC];       // 256 MB decoder_w^T (fp16)

// ---------------- prep ----------------------------------------------------------
__global__ void prep_x_kernel(const float* __restrict__ x,
                              const float* __restrict__ db) {
    int idx = blockIdx.x * blockDim.x + threadIdx.x;
    int b = idx >> 13;
    int r = (idx >> 10) & 7;
    int c = idx & 1023;
    float xc = x[idx] - db[r * CC + c];
    g_xc[idx] = xc;
    g_Ah[((size_t)r * BB + b) * CC + c] = __float2bfloat16(xc);
}

__global__ void prep_w_kernel(const float* __restrict__ ew) {
    int idx = blockIdx.x * blockDim.x + threadIdx.x;   // over R*D*C/8
    const float4* e4 = (const float4*)ew;
    float4 w0 = e4[2 * idx];
    float4 w1 = e4[2 * idx + 1];
    __nv_bfloat162 p0, p1, p2, p3;
    p0.x = __float2bfloat16(w0.x); p0.y = __float2bfloat16(w0.y);
    p1.x = __float2bfloat16(w0.z); p1.y = __float2bfloat16(w0.w);
    p2.x = __float2bfloat16(w1.x); p2.y = __float2bfloat16(w1.y);
    p3.x = __float2bfloat16(w1.z); p3.y = __float2bfloat16(w1.w);
    uint4 out;
    out.x = *(uint32_t*)&p0; out.y = *(uint32_t*)&p1;
    out.z = *(uint32_t*)&p2; out.w = *(uint32_t*)&p3;
    ((uint4*)g_Bh)[idx] = out;
}

// decoder_w transpose: [r][c][d] fp32 -> [r][d][c] fp16
__global__ void transpose_dw_kernel(const float* __restrict__ dw) {
    __shared__ float tile[32][33];
    int d0 = blockIdx.x * 32;
    int c0 = blockIdx.y * 32;
    int r  = blockIdx.z;
    int tx = threadIdx.x, ty = threadIdx.y;
    #pragma unroll
    for (int j = 0; j < 4; j++) {
        int c = c0 + ty + j * 8;
        tile[ty + j * 8][tx] = dw[((size_t)r * CC + c) * DD + d0 + tx];
    }
    __syncthreads();
    #pragma unroll
    for (int j = 0; j < 4; j++) {
        int d = d0 + ty + j * 8;
        g_dwT[((size_t)r * DD + d) * CC + c0 + tx] = __float2half(tile[tx][ty + j * 8]);
    }
}

// ---------------- encoder GEMM: bf16 mma m16n8k16, 4-stage cp.async + ldmatrix --
// Block 128x128, 8 warps (2x4), warp tile 64x32. Unroll-8 K loop (I$-safe).

__device__ __forceinline__ void mma16816(float* c, const uint32_t* a,
                                         uint32_t b0, uint32_t b1) {
    asm volatile(
        "mma.sync.aligned.m16n8k16.row.col.f32.bf16.bf16.f32 "
        "{%0,%1,%2,%3}, {%4,%5,%6,%7}, {%8,%9}, {%0,%1,%2,%3};\n"
        : "+f"(c[0]), "+f"(c[1]), "+f"(c[2]), "+f"(c[3])
        : "r"(a[0]), "r"(a[1]), "r"(a[2]), "r"(a[3]), "r"(b0), "r"(b1));
}

__device__ __forceinline__ void ldsm4(uint32_t* d, uint32_t addr) {
    asm volatile("ldmatrix.sync.aligned.m8n8.x4.shared.b16 {%0,%1,%2,%3}, [%4];"
                 : "=r"(d[0]), "=r"(d[1]), "=r"(d[2]), "=r"(d[3]) : "r"(addr));
}

__device__ __forceinline__ void cp16(uint32_t dst, const void* src) {
    asm volatile("cp.async.cg.shared.global [%0], [%1], 16;\n"
                 :: "r"(dst), "l"(src) : "memory");
}

__global__ __launch_bounds__(256, 2)
void encoder_gemm_kernel(const __nv_bfloat16* __restrict__ Ap,
                         const __nv_bfloat16* __restrict__ Bp,
                         const float* __restrict__ eb,
                         __half* __restrict__ H) {
    extern __shared__ uint8_t smem[];   // [NSTG][A|B][128*SSTB]
    const int mt = blockIdx.x;        // 8  (fastest: B-tile L2 reuse)
    const int nt = blockIdx.y;        // 128
    const int r  = blockIdx.z;        // 8
    const int tid = threadIdx.x;
    const int wid = tid >> 5, lane = tid & 31;
    const int wm = wid >> 2, wn = wid & 3;    // 2x4 warps, 64x32 per warp
    const int g = lane >> 2, t = lane & 3;

    float acc[4][4][4];
    #pragma unroll
    for (int i = 0; i < 4; i++)
        #pragma unroll
        for (int j = 0; j < 4; j++)
            #pragma unroll
            for (int q = 0; q < 4; q++) acc[i][j][q] = 0.f;

    const uint32_t s0 = (uint32_t)__cvta_generic_to_shared(smem);

    // global->smem: per operand-stage 128 rows x 64B = 512 x 16B; 2 per thread
    const int row0 = tid >> 2, seg0 = (tid & 3) * 8;            // seg in bf16 elems
    const int row1 = (tid + 256) >> 2, seg1 = ((tid + 256) & 3) * 8;
    const uint32_t d0b = (uint32_t)(row0 * SSTB + seg0 * 2);
    const uint32_t d1b = (uint32_t)(row1 * SSTB + seg1 * 2);

    // running global pointers (advance +32 elems per prefetched chunk)
    const __nv_bfloat16* pa0 = Ap + ((size_t)r * BB + (size_t)mt * 128 + row0) * CC + seg0;
    const __nv_bfloat16* pa1 = Ap + ((size_t)r * BB + (size_t)mt * 128 + row1) * CC + seg1;
    const __nv_bfloat16* pb0 = Bp + ((size_t)r * DD + (size_t)nt * 128 + row0) * CC + seg0;
    const __nv_bfloat16* pb1 = Bp + ((size_t)r * DD + (size_t)nt * 128 + row1) * CC + seg1;

    // ldmatrix lane offsets (bytes within operand-stage)
    const uint32_t aF = (uint32_t)((wm * 64 + (lane & 15)) * SSTB + (lane >> 4) * 16);
    const uint32_t bF = (uint32_t)((wn * 32 + (lane & 15)) * SSTB + (lane >> 4) * 16);

    #pragma unroll
    for (int p = 0; p < NSTG - 1; p++) {
        uint32_t aB = s0 + p * (2 * STG_BYTES);
        cp16(aB + d0b, pa0); cp16(aB + d1b, pa1);
        cp16(aB + STG_BYTES + d0b, pb0); cp16(aB + STG_BYTES + d1b, pb1);
        pa0 += 32; pa1 += 32; pb0 += 32; pb1 += 32;
        asm volatile("cp.async.commit_group;" ::: "memory");
    }

    const int NKT = CC / 32;   // 32
    #pragma unroll 8
    for (int kt = 0; kt < NKT; kt++) {
        asm volatile("cp.async.wait_group %0;" :: "n"(NSTG - 2) : "memory");
        __syncthreads();
        if (kt + NSTG - 1 < NKT) {
            const uint32_t aB = s0 + ((kt + NSTG - 1) & (NSTG - 1)) * (2 * STG_BYTES);
            cp16(aB + d0b, pa0); cp16(aB + d1b, pa1);
            cp16(aB + STG_BYTES + d0b, pb0); cp16(aB + STG_BYTES + d1b, pb1);
            pa0 += 32; pa1 += 32; pb0 += 32; pb1 += 32;
        }
        asm volatile("cp.async.commit_group;" ::: "memory");

        const uint32_t baseA = s0 + (kt & (NSTG - 1)) * (2 * STG_BYTES) + aF;
        const uint32_t baseB = s0 + (kt & (NSTG - 1)) * (2 * STG_BYTES) + STG_BYTES + bF;
        #pragma unroll
        for (int ks = 0; ks < 2; ks++) {          // two k16 steps per 64B row
            const int ko = ks * 32;               // byte offset (16 bf16)
            uint32_t afr[4][4], bq[2][4];
            #pragma unroll
            for (int mi = 0; mi < 4; mi++) ldsm4(afr[mi], baseA + mi * 16 * SSTB + ko);
            #pragma unroll
            for (int nb = 0; nb < 2; nb++) ldsm4(bq[nb], baseB + nb * 16 * SSTB + ko);
            #pragma unroll
            for (int mi = 0; mi < 4; mi++)
                #pragma unroll
                for (int nb = 0; nb < 2; nb++) {
                    mma16816(acc[mi][2 * nb],     afr[mi], bq[nb][0], bq[nb][2]);
                    mma16816(acc[mi][2 * nb + 1], afr[mi], bq[nb][1], bq[nb][3]);
                }
        }
    }

    // epilogue: h = acc + encoder_b -> fp16
    const size_t ebBase = (size_t)r * DD;
    #pragma unroll
    for (int mi = 0; mi < 4; mi++) {
        int b0 = mt * 128 + wm * 64 + mi * 16 + g;
        #pragma unroll
        for (int ni = 0; ni < 4; ni++) {
            int dd0 = nt * 128 + wn * 32 + ni * 8 + 2 * t;
            float e0 = eb[ebBase + dd0];
            float e1 = eb[ebBase + dd0 + 1];
            __half2 v0, v1;
            v0.x = __float2half(acc[mi][ni][0] + e0);
            v0.y = __float2half(acc[mi][ni][1] + e1);
            v1.x = __float2half(acc[mi][ni][2] + e0);
            v1.y = __float2half(acc[mi][ni][3] + e1);
            *(__half2*)&H[((size_t)b0 * RR + r) * DD + dd0]       = v0;
            *(__half2*)&H[((size_t)(b0 + 8) * RR + r) * DD + dd0] = v1;
        }
    }
}

// ---------------- fused select (topk->refine) + decode, one block per row -------
// block = r*BB + b (r-major: same-r blocks adjacent -> ew[r]/dwT[r] L2-resident)
__global__ __launch_bounds__(256)
void select_decode_kernel(const __half* __restrict__ H,
                          const float* __restrict__ ew,
                          const float* __restrict__ eb,
                          const float* __restrict__ db,
                          float* __restrict__ out) {
    __shared__ float sxc[CC];                 // 4 KB xc row
    __shared__ int   s_warp[8];
    __shared__ int   s_total, s_cnt, s_tiecnt;
    __shared__ int   scand[NCAND];
    __shared__ float sval[NCAND];
    __shared__ int   tie_idx[160];
    __shared__ float s_wval[KK];
    __shared__ int   s_widx[KK];

    const int r = blockIdx.x >> 10;
    const int b = blockIdx.x & 1023;
    const size_t row = (size_t)b * RR + r;            // h/xc/out row
    const int tid = threadIdx.x;              // 256 threads
    const int wid = tid >> 5, lane = tid & 31;

    // ---- phase 0: load xc row + h keys ----
    for (int i = tid; i < CC; i += 256) sxc[i] = g_xc[row * CC + i];

    const uint4* h4 = (const uint4*)(H + row * DD);
    uint32_t kreg[32];                        // 64 fp16 per thread, sortable u16 x2
    #pragma unroll
    for (int c = 0; c < 8; c++) {
        uint4 v = h4[tid + c * 256];
        uint32_t w[4] = {v.x, v.y, v.z, v.w};
        #pragma unroll
        for (int q = 0; q < 4; q++) {
            uint32_t x = w[q];
            uint32_t neg = (x >> 15) & 0x00010001u;
            kreg[c * 4 + q] = x ^ (0x80008000u | (neg * 0x7FFFu));
        }
    }

    // ---- phase 1: bisection for NCAND-th key ----
    int lo = -1, hi = 65535;
    for (int it = 0; it < 16; it++) {
        int mid = (lo + hi) >> 1;
        uint32_t m2 = (uint32_t)mid * 0x00010001u;
        uint32_t accv = 0;
        #pragma unroll
        for (int i = 0; i < 32; i++) accv += __vsetgtu2(kreg[i], m2);
        int cnt = (int)((accv & 0xFFFF) + (accv >> 16));
        #pragma unroll
        for (int o = 16; o > 0; o >>= 1) cnt += __shfl_xor_sync(0xFFFFFFFFu, cnt, o);
        if (lane == 0) s_warp[wid] = cnt;
        __syncthreads();
        if (tid == 0) {
            int tot = 0;
            #pragma unroll
            for (int w = 0; w < 8; w++) tot += s_warp[w];
            s_total = tot;
        }
        __syncthreads();
        if (s_total < NCAND) hi = mid; else lo = mid;
        __syncthreads();
    }
    const uint32_t T = (uint32_t)hi;

    if (tid == 0) { s_cnt = 0; s_tiecnt = 0; }
    __syncthreads();

    #pragma unroll
    for (int c = 0; c < 8; c++) {
        int ibase = (tid + c * 256) * 8;
        #pragma unroll
        for (int q = 0; q < 4; q++) {
            uint32_t k2 = kreg[c * 4 + q];
            uint32_t klo = k2 & 0xFFFF, khi = k2 >> 16;
            if (klo > T)       { int p = atomicAdd(&s_cnt, 1);    scand[p] = ibase + 2 * q; }
            else if (klo == T) { int p = atomicAdd(&s_tiecnt, 1); if (p < 160) tie_idx[p] = ibase + 2 * q; }
            if (khi > T)       { int p = atomicAdd(&s_cnt, 1);    scand[p] = ibase + 2 * q + 1; }
            else if (khi == T) { int p = atomicAdd(&s_tiecnt, 1); if (p < 160) tie_idx[p] = ibase + 2 * q + 1; }
        }
    }
    __syncthreads();
    if (tid == 0) {
        int gcnt = s_cnt;
        int need = NCAND - gcnt;              // >= 1
        for (int a = 0; a < need; a++) scand[gcnt + a] = tie_idx[a];
    }
    __syncthreads();

    // ---- phase 2: exact fp32 refine of NCAND candidates ----
    const float4* xs4 = (const float4*)sxc;
    #pragma unroll
    for (int j = 0; j < NCAND / 8; j++) {
        int ci = j * 8 + wid;                 // 5 rounds x 8 warps = 40
        int d = scand[ci];
        const float4* wr = (const float4*)(ew + ((size_t)r * DD + d) * CC);
        float acc = 0.f;
        #pragma unroll
        for (int it = 0; it < 8; it++) {
            float4 a = xs4[it * 32 + lane];
            float4 bv = wr[it * 32 + lane];
            acc += a.x * bv.x;
            acc += a.y * bv.y;
            acc += a.z * bv.z;
            acc += a.w * bv.w;
        }
        #pragma unroll
        for (int o = 16; o > 0; o >>= 1)
            acc += __shfl_xor_sync(0xFFFFFFFFu, acc, o);
        if (lane == 0) sval[ci] = acc + eb[(size_t)r * DD + d];
    }
    __syncthreads();

    // rank top-KK by (value desc, index asc); relu the values
    if (tid < NCAND) {
        float v = sval[tid];
        int   d = scand[tid];
        int rank = 0;
        #pragma unroll
        for (int j = 0; j < NCAND; j++) {
            float vj = sval[j];
            int   dj = scand[j];
            rank += (vj > v) || (vj == v && dj < d);
        }
        if (rank < KK) {
            s_widx[rank] = d;
            s_wval[rank] = v > 0.f ? v : 0.f;
        }
    }
    __syncthreads();

    // ---- phase 3: decode out = db + sum_j val_j * dwT[r][idx_j][:] (fp16 w) ----
    const __half2* dwr2 = (const __half2*)(g_dwT + (size_t)r * DD * CC);
    float4 acc4 = ((const float4*)(db + (size_t)r * CC))[tid];
    #pragma unroll
    for (int j = 0; j < KK; j++) {
        float vj = s_wval[j];
        const __half2* wrow = dwr2 + (size_t)s_widx[j] * (CC / 2) + tid * 2;
        float2 w01 = __half22float2(wrow[0]);
        float2 w23 = __half22float2(wrow[1]);
        acc4.x += vj * w01.x;
        acc4.y += vj * w01.y;
        acc4.z += vj * w23.x;
        acc4.w += vj * w23.y;
    }
    ((float4*)(out + row * CC))[tid] = acc4;
}

// ---------------- launch ----------------------------------------------------------
extern "C" void kernel_launch(void* const* d_in, const int* in_sizes, int n_in,
                              void* d_out, int out_size) {
    const float* x  = (const float*)d_in[0];
    const float* ew = (const float*)d_in[1];
    const float* eb = (const float*)d_in[2];
    const float* dw = (const float*)d_in[3];
    const float* db = (const float*)d_in[4];
    float* out = (float*)d_out;

    __half* h_ptr;         cudaGetSymbolAddress((void**)&h_ptr, g_h);
    __nv_bfloat16* a_ptr;  cudaGetSymbolAddress((void**)&a_ptr, g_Ah);
    __nv_bfloat16* b_ptr;  cudaGetSymbolAddress((void**)&b_ptr, g_Bh);

    cudaFuncSetAttribute(encoder_gemm_kernel,
                         cudaFuncAttributeMaxDynamicSharedMemorySize, GEMM_SMEM);

    prep_x_kernel<<<(BB * RR * CC) / 256, 256>>>(x, db);
    prep_w_kernel<<<(RR * DD * CC) / 2048, 256>>>(ew);
    transpose_dw_kernel<<<dim3(DD / 32, CC / 32, RR), dim3(32, 8)>>>(dw);
    encoder_gemm_kernel<<<dim3(BB / 128, DD / 128, RR), 256, GEMM_SMEM>>>(a_ptr, b_ptr, eb, h_ptr);
    select_decode_kernel<<<BB * RR, 256>>>(h_ptr, ew, eb, db, out);
}